// round 6
// baseline (speedup 1.0000x reference)
#include <cuda_runtime.h>
#include <cuda_bf16.h>

// PersistenceLandscapeLayer — single fused kernel, split-P with last-CTA merge.
// Grid (S x B): each CTA gathers CHUNK pairs, filters (death>birth && dim==d),
// compacts (center, halfwidth) to smem, computes per-chunk top-4 per (d,t) cell
// with dual independent insert chains, then the last CTA per batch row merges
// the S partials into the final [B, D, T, KMAX] output.
//
// tent(t) = max(min(t-b, d-t), 0) == max(hw - |t-c|, 0), c=(b+d)/2, hw=(d-b)/2.
// The explicit clamp is dropped: top-4 registers start at 0 and stay >= 0, so a
// negative candidate can never enter the chain (fmax rejects it at every rung).

constexpr int TT     = 32;
constexpr int D_HOM  = 2;
constexpr int KMAX   = 4;
constexpr int NCELL  = D_HOM * TT;          // 64 cells per batch row
constexpr int CHUNK  = 1024;                // pairs per CTA (2 per thread)
constexpr int NTH    = 512;
constexpr int MAXB   = 128;
constexpr int MAXS   = 8;                   // supports P up to 8192
constexpr unsigned FULL = 0xffffffffu;

// Scratch: per-(batch, split) partial top-4 per cell. 128*8*64*16B = 1MB.
__device__ float4 g_part[MAXB * MAXS * NCELL];
__device__ int    g_cnt[MAXB];              // zero-init; reset by last CTA

__global__ __launch_bounds__(NTH)
void pl_fused(const float* __restrict__ fun,
              const int*   __restrict__ bidx,
              const int*   __restrict__ didx,
              const int*   __restrict__ pdim,
              float*       __restrict__ out,
              int N, int P, int S)
{
    __shared__ __align__(16) float2 lst[D_HOM][CHUNK];  // (center, halfwidth)
    __shared__ int cnt[D_HOM];
    __shared__ int isLast;

    const int tid  = threadIdx.x;
    const int lane = tid & 31;
    const int ss   = blockIdx.x;            // split
    const int bb   = blockIdx.y;            // batch row

    const float* frow = fun  + (size_t)bb * N;
    const int*   brow = bidx + (size_t)bb * P;
    const int*   drow = didx + (size_t)bb * P;
    const int*   prow = pdim + (size_t)bb * P;

    if (tid < D_HOM) cnt[tid] = 0;
    __syncthreads();

    // ---- Phase 1: two pairs per thread, full-MLP gather + filter + compact ----
    {
        const int p0 = ss * CHUNK + 2 * tid;         // even -> int2 aligned
        bool act0 = (p0     < P);
        bool act1 = (p0 + 1 < P);
        int  bi0 = 0, bi1 = 0, di0 = 0, di1 = 0, dm0 = 0, dm1 = 0;
        if (act1) {
            int2 b2 = *(const int2*)(brow + p0);
            int2 d2 = *(const int2*)(drow + p0);
            int2 m2 = *(const int2*)(prow + p0);
            bi0 = b2.x; bi1 = b2.y; di0 = d2.x; di1 = d2.y; dm0 = m2.x; dm1 = m2.y;
        } else if (act0) {
            bi0 = brow[p0]; di0 = drow[p0]; dm0 = prow[p0];
        }
        float bv0 = 0.f, dv0 = 0.f, bv1 = 0.f, dv1 = 0.f;
        if (act0) { bv0 = __ldg(frow + bi0); dv0 = __ldg(frow + di0); }
        if (act1) { bv1 = __ldg(frow + bi1); dv1 = __ldg(frow + di1); }

        bool keep0 = act0 && (dv0 > bv0);
        bool keep1 = act1 && (dv1 > bv1);
        float c0 = (bv0 + dv0) * 0.5f, h0 = (dv0 - bv0) * 0.5f;
        float c1 = (bv1 + dv1) * 0.5f, h1 = (dv1 - bv1) * 0.5f;

        #pragma unroll
        for (int dd = 0; dd < D_HOM; ++dd) {
            #pragma unroll
            for (int sl = 0; sl < 2; ++sl) {
                bool mine = (sl == 0) ? (keep0 && dm0 == dd) : (keep1 && dm1 == dd);
                unsigned m = __ballot_sync(FULL, mine);
                if (m) {                              // warp-uniform
                    int leader = __ffs(m) - 1;
                    int cbase  = 0;
                    if (lane == leader) cbase = atomicAdd(&cnt[dd], __popc(m));
                    cbase = __shfl_sync(FULL, cbase, leader);
                    if (mine) {
                        int off = cbase + __popc(m & ((1u << lane) - 1u));
                        lst[dd][off] = (sl == 0) ? make_float2(c0, h0)
                                                 : make_float2(c1, h1);
                    }
                }
            }
        }
    }
    __syncthreads();
    // Pad each dim list to even length with a never-wins sentinel.
    if (tid < D_HOM) {
        int n = cnt[tid];
        if (n & 1) lst[tid][n] = make_float2(0.f, -1.f);
    }
    __syncthreads();

    // ---- Phase 2: one (d,t) cell per 8-lane subgroup; dual insert chains ----
    const int   w    = tid >> 5;
    const int   cell = (w << 2) + (lane >> 3);   // 0..63
    const int   dd   = cell >> 5;
    const int   t    = cell & (TT - 1);
    const int   sub  = lane & 7;
    const float tv   = (float)(t + 1) * (1.0f / (float)TT);
    const int   nv   = (cnt[dd] + 1) >> 1;       // # float4 packs
    const float4* L4 = (const float4*)lst[dd];

    float a0=0.f,a1=0.f,a2=0.f,a3=0.f;           // chain A (even candidates)
    float b0=0.f,b1=0.f,b2=0.f,b3=0.f;           // chain B (odd candidates)

    for (int k = sub; k < nv; k += 8) {
        float4 q = L4[k];                        // (c0,h0,c1,h1)
        float mA = q.y - fabsf(tv - q.x);
        float mB = q.w - fabsf(tv - q.z);
        float x;
        x = fmaxf(a0, mA); mA = fminf(a0, mA); a0 = x;
        x = fmaxf(b0, mB); mB = fminf(b0, mB); b0 = x;
        x = fmaxf(a1, mA); mA = fminf(a1, mA); a1 = x;
        x = fmaxf(b1, mB); mB = fminf(b1, mB); b1 = x;
        x = fmaxf(a2, mA); mA = fminf(a2, mA); a2 = x;
        x = fmaxf(b2, mB); mB = fminf(b2, mB); b2 = x;
        a3 = fmaxf(a3, mA);
        b3 = fmaxf(b3, mB);
    }

    // Merge chains A,B (both sorted desc): bitonic max-half + sort-4 desc.
    {
        float l0 = fmaxf(a0, b3), l1 = fmaxf(a1, b2);
        float l2 = fmaxf(a2, b1), l3 = fmaxf(a3, b0);
        float x0 = fmaxf(l0, l2), x2 = fminf(l0, l2);
        float x1 = fmaxf(l1, l3), x3 = fminf(l1, l3);
        a0 = fmaxf(x0, x1); a1 = fminf(x0, x1);
        a2 = fmaxf(x2, x3); a3 = fminf(x2, x3);
    }

    // 3-stage butterfly merge within the 8-lane subgroup.
    #pragma unroll
    for (int off = 4; off; off >>= 1) {
        float r0 = __shfl_xor_sync(FULL, a0, off);
        float r1 = __shfl_xor_sync(FULL, a1, off);
        float r2 = __shfl_xor_sync(FULL, a2, off);
        float r3 = __shfl_xor_sync(FULL, a3, off);
        float l0 = fmaxf(a0, r3), l1 = fmaxf(a1, r2);
        float l2 = fmaxf(a2, r1), l3 = fmaxf(a3, r0);
        float x0 = fmaxf(l0, l2), x2 = fminf(l0, l2);
        float x1 = fmaxf(l1, l3), x3 = fminf(l1, l3);
        a0 = fmaxf(x0, x1); a1 = fminf(x0, x1);
        a2 = fmaxf(x2, x3); a3 = fminf(x2, x3);
    }

    if (sub == 0) {
        g_part[((size_t)bb * S + ss) * NCELL + cell] = make_float4(a0, a1, a2, a3);
        __threadfence();                    // writer's partial visible device-wide
    }
    __syncthreads();                        // fences happen-before tid0's atomic

    // ---- Phase 3: last CTA of this batch row merges all S partials ----
    if (tid == 0) {
        int v = atomicAdd(&g_cnt[bb], 1);
        isLast = (v == S - 1);
        if (isLast) g_cnt[bb] = 0;          // reset for next graph replay
    }
    __syncthreads();

    if (isLast) {
        if (tid == 0) __threadfence();      // acquire side
        __syncthreads();
        if (tid < NCELL) {
            const float4* src = &g_part[(size_t)bb * S * NCELL + tid];
            float f0 = 0.f, f1 = 0.f, f2 = 0.f, f3 = 0.f;
            for (int s = 0; s < S; ++s) {
                float4 v = __ldcg(src + (size_t)s * NCELL);  // bypass stale L1
                float m, mx;
                #pragma unroll
                for (int k = 0; k < 4; ++k) {
                    m = (k == 0) ? v.x : (k == 1) ? v.y : (k == 2) ? v.z : v.w;
                    mx = fmaxf(f0, m); m = fminf(f0, m); f0 = mx;
                    mx = fmaxf(f1, m); m = fminf(f1, m); f1 = mx;
                    mx = fmaxf(f2, m); m = fminf(f2, m); f2 = mx;
                    f3 = fmaxf(f3, m);
                }
            }
            ((float4*)out)[(size_t)bb * NCELL + tid] = make_float4(f0, f1, f2, f3);
        }
    }
}

extern "C" void kernel_launch(void* const* d_in, const int* in_sizes, int n_in,
                              void* d_out, int out_size)
{
    const float* fun = (const float*)d_in[0];
    const int*   bi  = (const int*)  d_in[1];
    const int*   di  = (const int*)  d_in[2];
    const int*   pd  = (const int*)  d_in[3];
    float*       out = (float*)d_out;

    int B = out_size / (D_HOM * TT * KMAX);
    int N = in_sizes[0] / B;
    int P = in_sizes[1] / B;
    int S = (P + CHUNK - 1) / CHUNK;        // 4 for P=4096
    if (S > MAXS) S = MAXS;                 // scratch bound (never hit for P<=8192)

    dim3 g(S, B);
    pl_fused<<<g, NTH>>>(fun, bi, di, pd, out, N, P, S);
}

// round 9
// speedup vs baseline: 1.0971x; 1.0971x over previous
#include <cuda_runtime.h>
#include <cuda_bf16.h>

// PersistenceLandscapeLayer — fused split-P kernel, fine-grained CTAs.
// Grid (S=8 x B): 256-thread CTAs, CHUNK=512 pairs each. Gather+filter+compact
// (center,halfwidth) to smem, per-chunk top-4 per (d,t) cell (one cell per
// 4-lane subgroup, dual insert chains), last CTA per batch row merges.
//
// tent(t) = max(min(t-b, d-t), 0) == max(hw - |t-c|, 0). The clamp is dropped:
// top-4 regs start at 0 and stay >= 0, so negative candidates never enter.

constexpr int TT     = 32;
constexpr int D_HOM  = 2;
constexpr int KMAX   = 4;
constexpr int NCELL  = D_HOM * TT;          // 64 cells per batch row
constexpr int CHUNK  = 512;                 // pairs per CTA (2 per thread)
constexpr int NTH    = 256;
constexpr int MAXB   = 128;
constexpr int MAXS   = 16;                  // supports P up to 8192
constexpr unsigned FULL = 0xffffffffu;

// Scratch: per-(batch, split) partial top-4 per cell. 128*16*64*16B = 2MB.
__device__ float4 g_part[MAXB * MAXS * NCELL];
__device__ int    g_cnt[MAXB];              // zero-init; reset by last CTA

__global__ __launch_bounds__(NTH)
void pl_fused(const float* __restrict__ fun,
              const int*   __restrict__ bidx,
              const int*   __restrict__ didx,
              const int*   __restrict__ pdim,
              float*       __restrict__ out,
              int N, int P, int S)
{
    __shared__ __align__(16) float2 lst[D_HOM][CHUNK];  // (center, halfwidth)
    __shared__ int cnt[D_HOM];
    __shared__ int isLast;

    const int tid  = threadIdx.x;
    const int lane = tid & 31;
    const int ss   = blockIdx.x;            // split
    const int bb   = blockIdx.y;            // batch row

    const float* frow = fun  + (size_t)bb * N;
    const int*   brow = bidx + (size_t)bb * P;
    const int*   drow = didx + (size_t)bb * P;
    const int*   prow = pdim + (size_t)bb * P;

    if (tid < D_HOM) cnt[tid] = 0;
    __syncthreads();

    // ---- Phase 1: two pairs per thread, full-MLP gather + filter + compact ----
    {
        const int p0 = ss * CHUNK + 2 * tid;         // even -> int2 aligned
        bool act0 = (p0     < P);
        bool act1 = (p0 + 1 < P);
        int  bi0 = 0, bi1 = 0, di0 = 0, di1 = 0, dm0 = 0, dm1 = 0;
        if (act1) {
            int2 b2 = *(const int2*)(brow + p0);
            int2 d2 = *(const int2*)(drow + p0);
            int2 m2 = *(const int2*)(prow + p0);
            bi0 = b2.x; bi1 = b2.y; di0 = d2.x; di1 = d2.y; dm0 = m2.x; dm1 = m2.y;
        } else if (act0) {
            bi0 = brow[p0]; di0 = drow[p0]; dm0 = prow[p0];
        }
        float bv0 = 0.f, dv0 = 0.f, bv1 = 0.f, dv1 = 0.f;
        if (act0) { bv0 = __ldcg(frow + bi0); dv0 = __ldcg(frow + di0); }
        if (act1) { bv1 = __ldcg(frow + bi1); dv1 = __ldcg(frow + di1); }

        bool keep0 = act0 && (dv0 > bv0);
        bool keep1 = act1 && (dv1 > bv1);
        float c0 = (bv0 + dv0) * 0.5f, h0 = (dv0 - bv0) * 0.5f;
        float c1 = (bv1 + dv1) * 0.5f, h1 = (dv1 - bv1) * 0.5f;

        #pragma unroll
        for (int dd = 0; dd < D_HOM; ++dd) {
            #pragma unroll
            for (int sl = 0; sl < 2; ++sl) {
                bool mine = (sl == 0) ? (keep0 && dm0 == dd) : (keep1 && dm1 == dd);
                unsigned m = __ballot_sync(FULL, mine);
                if (m) {                              // warp-uniform
                    int leader = __ffs(m) - 1;
                    int cbase  = 0;
                    if (lane == leader) cbase = atomicAdd(&cnt[dd], __popc(m));
                    cbase = __shfl_sync(FULL, cbase, leader);
                    if (mine) {
                        int off = cbase + __popc(m & ((1u << lane) - 1u));
                        lst[dd][off] = (sl == 0) ? make_float2(c0, h0)
                                                 : make_float2(c1, h1);
                    }
                }
            }
        }
    }
    __syncthreads();
    // Pad each dim list to even length with a never-wins sentinel.
    if (tid < D_HOM) {
        int n = cnt[tid];
        if (n & 1) lst[tid][n] = make_float2(0.f, -1.f);
    }
    __syncthreads();

    // ---- Phase 2: one (d,t) cell per 4-lane subgroup; dual insert chains ----
    const int   w    = tid >> 5;                 // 0..7
    const int   cell = (w << 3) + (lane >> 2);   // 0..63
    const int   dd   = cell >> 5;
    const int   t    = cell & (TT - 1);
    const int   sub  = lane & 3;
    const float tv   = (float)(t + 1) * (1.0f / (float)TT);
    const int   nv   = (cnt[dd] + 1) >> 1;       // # float4 packs
    const float4* L4 = (const float4*)lst[dd];

    float a0=0.f,a1=0.f,a2=0.f,a3=0.f;           // chain A (even candidates)
    float b0=0.f,b1=0.f,b2=0.f,b3=0.f;           // chain B (odd candidates)

    #pragma unroll 4
    for (int k = sub; k < nv; k += 4) {
        float4 q = L4[k];                        // (c0,h0,c1,h1) broadcast
        float mA = q.y - fabsf(tv - q.x);
        float mB = q.w - fabsf(tv - q.z);
        float x;
        x = fmaxf(a0, mA); mA = fminf(a0, mA); a0 = x;
        x = fmaxf(b0, mB); mB = fminf(b0, mB); b0 = x;
        x = fmaxf(a1, mA); mA = fminf(a1, mA); a1 = x;
        x = fmaxf(b1, mB); mB = fminf(b1, mB); b1 = x;
        x = fmaxf(a2, mA); mA = fminf(a2, mA); a2 = x;
        x = fmaxf(b2, mB); mB = fminf(b2, mB); b2 = x;
        a3 = fmaxf(a3, mA);
        b3 = fmaxf(b3, mB);
    }

    // Merge chains A,B (both sorted desc): bitonic max-half + sort-4 desc.
    {
        float l0 = fmaxf(a0, b3), l1 = fmaxf(a1, b2);
        float l2 = fmaxf(a2, b1), l3 = fmaxf(a3, b0);
        float x0 = fmaxf(l0, l2), x2 = fminf(l0, l2);
        float x1 = fmaxf(l1, l3), x3 = fminf(l1, l3);
        a0 = fmaxf(x0, x1); a1 = fminf(x0, x1);
        a2 = fmaxf(x2, x3); a3 = fminf(x2, x3);
    }

    // 2-stage butterfly merge within the 4-lane subgroup.
    #pragma unroll
    for (int off = 2; off; off >>= 1) {
        float r0 = __shfl_xor_sync(FULL, a0, off);
        float r1 = __shfl_xor_sync(FULL, a1, off);
        float r2 = __shfl_xor_sync(FULL, a2, off);
        float r3 = __shfl_xor_sync(FULL, a3, off);
        float l0 = fmaxf(a0, r3), l1 = fmaxf(a1, r2);
        float l2 = fmaxf(a2, r1), l3 = fmaxf(a3, r0);
        float x0 = fmaxf(l0, l2), x2 = fminf(l0, l2);
        float x1 = fmaxf(l1, l3), x3 = fminf(l1, l3);
        a0 = fmaxf(x0, x1); a1 = fminf(x0, x1);
        a2 = fmaxf(x2, x3); a3 = fminf(x2, x3);
    }

    if (sub == 0) {
        g_part[((size_t)bb * S + ss) * NCELL + cell] = make_float4(a0, a1, a2, a3);
        __threadfence();                    // writer's partial visible device-wide
    }
    __syncthreads();                        // fences happen-before tid0's atomic

    // ---- Phase 3: last CTA of this batch row merges all S partials ----
    if (tid == 0) {
        int v = atomicAdd(&g_cnt[bb], 1);
        isLast = (v == S - 1);
        if (isLast) g_cnt[bb] = 0;          // reset for next graph replay
    }
    __syncthreads();

    if (isLast) {
        if (tid == 0) __threadfence();      // acquire side
        __syncthreads();
        if (tid < NCELL) {
            const float4* src = &g_part[(size_t)bb * S * NCELL + tid];
            float f0 = 0.f, f1 = 0.f, f2 = 0.f, f3 = 0.f;
            for (int s = 0; s < S; ++s) {
                float4 v = __ldcg(src + (size_t)s * NCELL);  // bypass stale L1
                float m, mx;
                #pragma unroll
                for (int k = 0; k < 4; ++k) {
                    m = (k == 0) ? v.x : (k == 1) ? v.y : (k == 2) ? v.z : v.w;
                    mx = fmaxf(f0, m); m = fminf(f0, m); f0 = mx;
                    mx = fmaxf(f1, m); m = fminf(f1, m); f1 = mx;
                    mx = fmaxf(f2, m); m = fminf(f2, m); f2 = mx;
                    f3 = fmaxf(f3, m);
                }
            }
            ((float4*)out)[(size_t)bb * NCELL + tid] = make_float4(f0, f1, f2, f3);
        }
    }
}

extern "C" void kernel_launch(void* const* d_in, const int* in_sizes, int n_in,
                              void* d_out, int out_size)
{
    const float* fun = (const float*)d_in[0];
    const int*   bi  = (const int*)  d_in[1];
    const int*   di  = (const int*)  d_in[2];
    const int*   pd  = (const int*)  d_in[3];
    float*       out = (float*)d_out;

    int B = out_size / (D_HOM * TT * KMAX);
    int N = in_sizes[0] / B;
    int P = in_sizes[1] / B;
    int S = (P + CHUNK - 1) / CHUNK;        // 8 for P=4096
    if (S > MAXS) S = MAXS;                 // scratch bound (never hit for P<=8192)

    dim3 g(S, B);
    pl_fused<<<g, NTH>>>(fun, bi, di, pd, out, N, P, S);
}